// round 1
// baseline (speedup 1.0000x reference)
#include <cuda_runtime.h>
#include <math.h>

#define BATCH 64
#define IC 32
#define OC 32
#define NM 64
#define HW 4096
#define CTRLD 512
#define ROWS 4160        // NF(64) + NI(2048) + NO(2048)
#define KSPLIT 2
#define OUT_ELEMS (BATCH * OC * HW)   // 8388608, new_state follows in d_out

// scratch for control-GEMM partials: [ksplit][batch][row]
__device__ float g_ctrl[KSPLIT * BATCH * ROWS];

// ---------------------------------------------------------------------------
// Kernel 1: ctrl = controls @ W.T   (C[r][b] = sum_k W[r,k] * controls[b,k])
// grid (65, 2): 64 rows x 64 batches per block, K split in halves of 256.
// ---------------------------------------------------------------------------
__global__ __launch_bounds__(256) void ctrl_gemm(
    const float* __restrict__ controls,   // [64, 512]
    const float* __restrict__ W)          // [4160, 512]
{
    __shared__ float sW[32 * 68];   // [k][r], padded row 68
    __shared__ float sC[32 * 68];   // [k][b], padded row 68

    const int r0    = blockIdx.x * 64;
    const int kz    = blockIdx.y;
    const int kbase = kz * 256;
    const int tid   = threadIdx.x;
    const int ty    = tid >> 4;     // 0..15 -> row sub-tile
    const int tx    = tid & 15;     // 0..15 -> batch sub-tile

    float acc[4][4] = {};

    for (int kc0 = 0; kc0 < 256; kc0 += 32) {
        // stage tiles (coalesced gmem, padded smem)
        #pragma unroll
        for (int i = tid; i < 64 * 32; i += 256) {
            int r = i >> 5, k = i & 31;
            sW[k * 68 + r] = W[(size_t)(r0 + r) * CTRLD + kbase + kc0 + k];
        }
        #pragma unroll
        for (int i = tid; i < 64 * 32; i += 256) {
            int b = i >> 5, k = i & 31;
            sC[k * 68 + b] = controls[b * CTRLD + kbase + kc0 + k];
        }
        __syncthreads();

        #pragma unroll
        for (int k = 0; k < 32; k++) {
            float4 a  = *(const float4*)&sW[k * 68 + ty * 4];
            float4 bb = *(const float4*)&sC[k * 68 + tx * 4];
            float av[4] = {a.x, a.y, a.z, a.w};
            float bv[4] = {bb.x, bb.y, bb.z, bb.w};
            #pragma unroll
            for (int i = 0; i < 4; i++)
                #pragma unroll
                for (int j = 0; j < 4; j++)
                    acc[i][j] = fmaf(av[i], bv[j], acc[i][j]);
        }
        __syncthreads();
    }

    #pragma unroll
    for (int i = 0; i < 4; i++) {
        int r = r0 + ty * 4 + i;
        #pragma unroll
        for (int j = 0; j < 4; j++) {
            int b = tx * 4 + j;
            g_ctrl[kz * (BATCH * ROWS) + b * ROWS + r] = acc[i][j];
        }
    }
}

// ---------------------------------------------------------------------------
// Kernel 2: fused gated-input GEMM + state update + tanh + output GEMM.
// grid (HW/128, BATCH), 256 threads, 128 pixels per block.
// ---------------------------------------------------------------------------
__global__ __launch_bounds__(256, 2) void vstm_main(
    const float* __restrict__ inputs,     // [B, 32, 4096]
    const float* __restrict__ state,      // [B, 64, 4096]
    float* __restrict__ outputs,          // [B, 32, 4096]
    float* __restrict__ new_state)        // [B, 64, 4096]
{
    extern __shared__ float sm[];
    float* s_in   = sm;                     // [32][128]
    float* s_t    = s_in + 32 * 128;        // [64][128]
    float* s_gin  = s_t + 64 * 128;         // [c][m], row 68
    float* s_gout = s_gin + 32 * 68;        // [m][o], row 36
    float* s_f    = s_gout + 64 * 36;       // [64]

    const int b   = blockIdx.y;
    const int p0  = blockIdx.x * 128;
    const int tid = threadIdx.x;

    // ---- stage gates (sum the two K-split partials) ----
    const float* gc0 = g_ctrl + b * ROWS;
    const float* gc1 = g_ctrl + BATCH * ROWS + b * ROWS;
    for (int i = tid; i < ROWS; i += 256) {
        float v = gc0[i] + gc1[i];
        if (i < 64) {
            s_f[i] = v;                                   // forget gate [m]
        } else if (i < 64 + 2048) {
            int j = i - 64;                               // in_gates [m][c]
            s_gin[(j & 31) * 68 + (j >> 5)] = v;          // -> [c][m]
        } else {
            int j = i - 2112;                             // out_gates [o][m]
            s_gout[(j & 63) * 36 + (j >> 6)] = v;         // -> [m][o]
        }
    }

    // ---- stage input tile [32][128] ----
    const float* inb = inputs + (size_t)b * (IC * HW) + p0;
    #pragma unroll
    for (int i = tid; i < 32 * 32; i += 256) {
        int c = i >> 5, p4 = i & 31;
        *(float4*)&s_in[c * 128 + p4 * 4] = *(const float4*)&inb[c * 4096 + p4 * 4];
    }
    __syncthreads();

    const int tx = tid & 31;     // pixel sub-tile: 4 pixels
    const int ty = tid >> 5;     // 0..7
    const int pp = tx * 4;

    // ---- phase 1: gated = gin(64x32) @ in(32x128); thread = 8m x 4p ----
    {
        const int m0 = ty * 8;
        float acc[8][4] = {};
        #pragma unroll
        for (int c = 0; c < 32; c++) {
            float4 a0 = *(const float4*)&s_gin[c * 68 + m0];      // broadcast per warp
            float4 a1 = *(const float4*)&s_gin[c * 68 + m0 + 4];
            float4 bb = *(const float4*)&s_in[c * 128 + pp];
            float av[8] = {a0.x, a0.y, a0.z, a0.w, a1.x, a1.y, a1.z, a1.w};
            float bv[4] = {bb.x, bb.y, bb.z, bb.w};
            #pragma unroll
            for (int i = 0; i < 8; i++)
                #pragma unroll
                for (int j = 0; j < 4; j++)
                    acc[i][j] = fmaf(av[i], bv[j], acc[i][j]);
        }

        const float* stb = state + (size_t)b * (NM * HW) + p0 + pp;
        float*       nsb = new_state + (size_t)b * (NM * HW) + p0 + pp;
        #pragma unroll
        for (int i = 0; i < 8; i++) {
            int m = m0 + i;
            float f = s_f[m];
            float4 st = *(const float4*)&stb[(size_t)m * 4096];
            float4 ns;
            ns.x = fmaf(st.x, f, acc[i][0]);
            ns.y = fmaf(st.y, f, acc[i][1]);
            ns.z = fmaf(st.z, f, acc[i][2]);
            ns.w = fmaf(st.w, f, acc[i][3]);
            *(float4*)&nsb[(size_t)m * 4096] = ns;
            float4 t;
            t.x = tanhf(ns.x);
            t.y = tanhf(ns.y);
            t.z = tanhf(ns.z);
            t.w = tanhf(ns.w);
            *(float4*)&s_t[m * 128 + pp] = t;
        }
    }
    __syncthreads();

    // ---- phase 2: out = gout(32x64) @ t(64x128); thread = 4o x 4p ----
    {
        const int o0 = ty * 4;
        float acc[4][4] = {};
        #pragma unroll
        for (int m = 0; m < 64; m++) {
            float4 a  = *(const float4*)&s_gout[m * 36 + o0];     // broadcast per warp
            float4 bb = *(const float4*)&s_t[m * 128 + pp];
            float av[4] = {a.x, a.y, a.z, a.w};
            float bv[4] = {bb.x, bb.y, bb.z, bb.w};
            #pragma unroll
            for (int i = 0; i < 4; i++)
                #pragma unroll
                for (int j = 0; j < 4; j++)
                    acc[i][j] = fmaf(av[i], bv[j], acc[i][j]);
        }

        float* ob = outputs + (size_t)b * (OC * HW) + p0 + pp;
        #pragma unroll
        for (int i = 0; i < 4; i++) {
            float4 v = make_float4(acc[i][0], acc[i][1], acc[i][2], acc[i][3]);
            *(float4*)&ob[(size_t)(o0 + i) * 4096] = v;
        }
    }
}

// ---------------------------------------------------------------------------
extern "C" void kernel_launch(void* const* d_in, const int* in_sizes, int n_in,
                              void* d_out, int out_size) {
    const float* inputs   = (const float*)d_in[0];   // [64,32,64,64]
    const float* state    = (const float*)d_in[1];   // [64,64,64,64]
    const float* controls = (const float*)d_in[2];   // [64,512]
    const float* W        = (const float*)d_in[3];   // [4160,512]

    float* outputs   = (float*)d_out;                // first 8388608 elems
    float* new_state = outputs + OUT_ELEMS;          // next 16777216 elems

    ctrl_gemm<<<dim3(65, 2), 256>>>(controls, W);

    const size_t smem = (32 * 128 + 64 * 128 + 32 * 68 + 64 * 36 + 64) * sizeof(float);
    cudaFuncSetAttribute(vstm_main, cudaFuncAttributeMaxDynamicSharedMemorySize, (int)smem);
    vstm_main<<<dim3(HW / 128, BATCH), 256, smem>>>(inputs, state, outputs, new_state);
}